// round 7
// baseline (speedup 1.0000x reference)
#include <cuda_runtime.h>
#include <cstdint>

#define MTOK 16384
#define FDIM 4096
#define CDIM 1024
#define NQ 8

#define BM 128
#define BN 128
#define BK 32
#define STAGES 3
#define KTILES (FDIM / BK)          // 128
#define ROWF 36                      // padded floats per smem row (conflict-free frags)
#define A_FLOATS (BM * ROWF)         // 4608
#define STAGE_FLOATS (2 * A_FLOATS)  // A then B
#define SMEM_TOTAL (STAGES * STAGE_FLOATS * 4)   // 110592 B

// ---- scratch (device globals; allocation is forbidden) ----
__device__ __align__(128) float g_q[MTOK * NQ];                 // 512 KB
__device__ __align__(128) float g_h[(size_t)MTOK * FDIM];       // 256 MB
__device__ __align__(128) float g_w2r[(size_t)CDIM * FDIM];     // 16 MB

__device__ __forceinline__ uint32_t smem_u32(const void* p) {
    uint32_t a;
    asm("{ .reg .u64 t; cvta.to.shared.u64 t, %1; cvt.u32.u64 %0, t; }" : "=r"(a) : "l"(p));
    return a;
}

__device__ __forceinline__ float tf32r(float x) {
    uint32_t y;
    asm("cvt.rna.tf32.f32 %0, %1;" : "=r"(y) : "f"(x));
    return __uint_as_float(y);
}

__device__ __forceinline__ void cp_async16(uint32_t dst, const void* src) {
    asm volatile("cp.async.cg.shared.global [%0], [%1], 16;" :: "r"(dst), "l"(src));
}
#define CP_COMMIT() asm volatile("cp.async.commit_group;" ::: "memory")
#define CP_WAIT2()  asm volatile("cp.async.wait_group 2;" ::: "memory")

__device__ __forceinline__ void mma_tf32(float* c, const uint32_t* a, uint32_t b0, uint32_t b1) {
    asm volatile(
        "mma.sync.aligned.m16n8k8.row.col.f32.tf32.tf32.f32 "
        "{%0,%1,%2,%3}, {%4,%5,%6,%7}, {%8,%9}, {%0,%1,%2,%3};"
        : "+f"(c[0]), "+f"(c[1]), "+f"(c[2]), "+f"(c[3])
        : "r"(a[0]), "r"(a[1]), "r"(a[2]), "r"(a[3]), "r"(b0), "r"(b1));
}

// ==================== pass 0: q = cumprod(cos(x[:, :8])) ====================
__global__ void __launch_bounds__(256) q_kernel(const float* __restrict__ x) {
    int tok = blockIdx.x * 256 + threadIdx.x;
    const float4* xp = (const float4*)(x + (size_t)tok * CDIM);
    float4 a = xp[0], b = xp[1];
    float q0 = cosf(a.x);
    float q1 = q0 * cosf(a.y);
    float q2 = q1 * cosf(a.z);
    float q3 = q2 * cosf(a.w);
    float q4 = q3 * cosf(b.x);
    float q5 = q4 * cosf(b.y);
    float q6 = q5 * cosf(b.z);
    float q7 = q6 * cosf(b.w);
    float4* qp = (float4*)(g_q + (size_t)tok * NQ);
    qp[0] = make_float4(q0, q1, q2, q3);
    qp[1] = make_float4(q4, q5, q6, q7);
}

// ==================== pass 0b: w2 rounded to tf32-nearest ====================
__global__ void __launch_bounds__(256) round_w2_kernel(const float* __restrict__ w2) {
    size_t i = (size_t)(blockIdx.x * 256 + threadIdx.x) * 4;
    float4 v = *(const float4*)(w2 + i);
    v.x = tf32r(v.x); v.y = tf32r(v.y); v.z = tf32r(v.z); v.w = tf32r(v.w);
    *(float4*)(g_w2r + i) = v;
}

// ==================== pass 1: h = relu(q @ w1^T + b1), tf32-rounded ====================
__global__ void __launch_bounds__(256) h_kernel(const float* __restrict__ w1,
                                                const float* __restrict__ b1) {
    __shared__ float qs[512 * NQ];  // 16 KB
    int t = threadIdx.x;
    const float4* qg = (const float4*)(g_q + (size_t)blockIdx.y * 512 * NQ);
    float4* qs4 = (float4*)qs;
#pragma unroll
    for (int i = 0; i < 4; i++) qs4[t + i * 256] = qg[t + i * 256];
    __syncthreads();

    int f = blockIdx.x * 32 + (t & 31);
    int tok0 = (t >> 5) * 64;
    float4 wa = __ldg((const float4*)(w1 + (size_t)f * NQ));
    float4 wb = __ldg((const float4*)(w1 + (size_t)f * NQ + 4));
    float bias = __ldg(b1 + f);
    float* hp = g_h + ((size_t)(blockIdx.y * 512 + tok0)) * FDIM + f;

#pragma unroll 8
    for (int i = 0; i < 64; i++) {
        const float4* qr = (const float4*)(qs + (tok0 + i) * NQ);
        float4 qa = qr[0], qb = qr[1];
        float v = bias;
        v = fmaf(qa.x, wa.x, v); v = fmaf(qa.y, wa.y, v);
        v = fmaf(qa.z, wa.z, v); v = fmaf(qa.w, wa.w, v);
        v = fmaf(qb.x, wb.x, v); v = fmaf(qb.y, wb.y, v);
        v = fmaf(qb.z, wb.z, v); v = fmaf(qb.w, wb.w, v);
        hp[(size_t)i * FDIM] = tf32r(fmaxf(v, 0.0f));
    }
}

// ==================== pass 2: out = h @ w2^T + b2 (mma.sync tf32) ====================
// Smem tile layout: A[128][36] floats (rows = m, 32 k-cols + 4 pad), B[128][36] (rows = n).
// cp.async fills rows in 8 chunks of 16B; pad keeps 16B alignment (36*4=144).
__device__ __forceinline__ void load_tile(uint32_t stage_b, int m0, int n0, int k0, int tid) {
#pragma unroll
    for (int i = 0; i < 4; i++) {
        int idx = tid + i * 256;
        int row = idx >> 3, c4 = idx & 7;
        cp_async16(stage_b + (row * ROWF + c4 * 4) * 4,
                   g_h + (size_t)(m0 + row) * FDIM + k0 + c4 * 4);
    }
#pragma unroll
    for (int i = 0; i < 4; i++) {
        int idx = tid + i * 256;
        int row = idx >> 3, c4 = idx & 7;
        cp_async16(stage_b + (A_FLOATS + row * ROWF + c4 * 4) * 4,
                   g_w2r + (size_t)(n0 + row) * FDIM + k0 + c4 * 4);
    }
}

__global__ void __launch_bounds__(256, 2) gemm2_kernel(const float* __restrict__ b2,
                                                       float* __restrict__ out) {
    extern __shared__ __align__(16) uint32_t sm[];
    uint32_t sb = smem_u32(sm);
    int tid = threadIdx.x, wid = tid >> 5, lane = tid & 31;
    int wm = wid & 3, wn = wid >> 2;          // warp grid 4 x 2; warp tile 32 x 64
    int g = lane >> 2, t4 = lane & 3;
    int m0 = blockIdx.y * BM, n0 = blockIdx.x * BN;

    float acc[2][8][4];
#pragma unroll
    for (int mt = 0; mt < 2; mt++)
#pragma unroll
        for (int nt = 0; nt < 8; nt++)
#pragma unroll
            for (int r = 0; r < 4; r++) acc[mt][nt][r] = 0.0f;

    // prologue: tiles 0,1
    load_tile(sb, m0, n0, 0, tid);               CP_COMMIT();
    load_tile(sb + STAGE_FLOATS * 4, m0, n0, BK, tid); CP_COMMIT();

    // per-warp smem base rows (element indices into uint32_t smem)
    const uint32_t aRow0 = (uint32_t)(wm * 32 + g) * ROWF;
    const uint32_t bRow0 = (uint32_t)(A_FLOATS + (wn * 64 + g) * ROWF);

    for (int t = 0; t < KTILES; t++) {
        if (t + 2 < KTILES)
            load_tile(sb + ((t + 2) % STAGES) * STAGE_FLOATS * 4, m0, n0, (t + 2) * BK, tid);
        CP_COMMIT();
        CP_WAIT2();
        __syncthreads();

        const uint32_t* st = sm + (t % STAGES) * STAGE_FLOATS;
#pragma unroll
        for (int ks = 0; ks < 4; ks++) {
            int k8 = ks * 8 + t4;
            uint32_t a[2][4];
#pragma unroll
            for (int mt = 0; mt < 2; mt++) {
                uint32_t r0 = aRow0 + mt * 16 * ROWF;
                a[mt][0] = st[r0 + k8];
                a[mt][1] = st[r0 + 8 * ROWF + k8];
                a[mt][2] = st[r0 + k8 + 4];
                a[mt][3] = st[r0 + 8 * ROWF + k8 + 4];
            }
#pragma unroll
            for (int nt = 0; nt < 8; nt++) {
                uint32_t rb = bRow0 + nt * 8 * ROWF;
                uint32_t b0 = st[rb + k8];
                uint32_t b1 = st[rb + k8 + 4];
                mma_tf32(acc[0][nt], a[0], b0, b1);
                mma_tf32(acc[1][nt], a[1], b0, b1);
            }
        }
        __syncthreads();
    }

    // epilogue: c0/c1 at (row g, cols 2t4, 2t4+1), c2/c3 at row g+8
#pragma unroll
    for (int mt = 0; mt < 2; mt++) {
        int mrow = m0 + wm * 32 + mt * 16 + g;
#pragma unroll
        for (int nt = 0; nt < 8; nt++) {
            int nc = n0 + wn * 64 + nt * 8 + 2 * t4;
            float bx = __ldg(b2 + nc), by = __ldg(b2 + nc + 1);
            float2 v0 = make_float2(acc[mt][nt][0] + bx, acc[mt][nt][1] + by);
            float2 v1 = make_float2(acc[mt][nt][2] + bx, acc[mt][nt][3] + by);
            *(float2*)(out + (size_t)mrow * CDIM + nc) = v0;
            *(float2*)(out + (size_t)(mrow + 8) * CDIM + nc) = v1;
        }
    }
}

// ==================== launch ====================
extern "C" void kernel_launch(void* const* d_in, const int* in_sizes, int n_in,
                              void* d_out, int out_size) {
    const float* x  = (const float*)d_in[0];
    // d_in[1] = circuit_params: provably cancels out of the measured expectations
    const float* w1 = (const float*)d_in[2];
    const float* b1 = (const float*)d_in[3];
    const float* w2 = (const float*)d_in[4];
    const float* b2 = (const float*)d_in[5];
    float* out = (float*)d_out;

    q_kernel<<<MTOK / 256, 256>>>(x);
    round_w2_kernel<<<(CDIM * FDIM) / (256 * 4), 256>>>(w2);
    h_kernel<<<dim3(FDIM / 32, MTOK / 512), 256>>>(w1, b1);

    cudaFuncSetAttribute(gemm2_kernel, cudaFuncAttributeMaxDynamicSharedMemorySize, SMEM_TOTAL);
    gemm2_kernel<<<dim3(CDIM / BN, MTOK / BM), 256, SMEM_TOTAL>>>(b2, out);
}